// round 7
// baseline (speedup 1.0000x reference)
#include <cuda_runtime.h>
#include <cstdint>

#define Uv 2048
#define Bv 16
#define Tv 2048
#define Fv 128
#define NCTA 128
#define CPC 16
#define TK 256
#define WSTR 2052
#define SMEM_MAIN ((CPC*WSTR + 2*TK*16) * 4)

typedef unsigned long long u64;

__device__ __align__(16) float g_u[(size_t)Tv * Uv * Bv];   // [t][u][b]
__device__ __align__(16) float g_h[2][Uv * Bv];             // [buf][u][b]
__device__ unsigned g_bar;
__device__ int   g_ci[Uv * 16];   // CSC: f-indices per u
__device__ float g_cv[Uv * 16];   // CSC: values per u
__device__ int   g_cn[Uv];        // CSC: counts

__device__ __forceinline__ void fma2(u64& d, u64 a, u64 b) {
    asm("fma.rn.f32x2 %0, %1, %2, %0;" : "+l"(d) : "l"(a), "l"(b));
}
__device__ __forceinline__ void add2(u64& d, u64 a) {
    asm("add.rn.f32x2 %0, %1, %0;" : "+l"(d) : "l"(a));
}
__device__ __forceinline__ u64 dup32(float x) {
    u64 d; unsigned xi = __float_as_uint(x);
    asm("mov.b64 %0, {%1, %1};" : "=l"(d) : "r"(xi)); return d;
}
__device__ __forceinline__ unsigned sptr(const void* p) {
    unsigned r;
    asm("{ .reg .u64 t; cvta.to.shared.u64 t, %1; cvt.u32.u64 %0, t; }" : "=r"(r) : "l"(p));
    return r;
}
__device__ __forceinline__ void cpa16(unsigned dst, const float* src) {
    asm volatile("cp.async.cg.shared.global [%0], [%1], 16;" :: "r"(dst), "l"(src));
}
__device__ __forceinline__ unsigned ldacq(unsigned* p) {
    unsigned v;
    asm volatile("ld.acquire.gpu.u32 %0, [%1];" : "=r"(v) : "l"(p) : "memory");
    return v;
}

__global__ void k0() {
    int i = blockIdx.x * blockDim.x + threadIdx.x;
    if (i == 0) g_bar = 0u;
    if (i < Uv * Bv) g_h[0][i] = 0.0f;
}

// Build sparse column lists of kernel[F,U], deterministic (f ascending).
__global__ void k_csc(const float* __restrict__ kern) {
    int u = blockIdx.x * blockDim.x + threadIdx.x;
    if (u >= Uv) return;
    int c = 0;
    for (int f = 0; f < Fv; f++) {
        float v = kern[(size_t)f * Uv + u];
        if (v != 0.0f) {
            g_ci[u * 16 + c] = f;
            g_cv[u * 16 + c] = v;
            c++;
        }
    }
    g_cn[u] = c;
}

// g_u[t][u][b] = bias[u] + sparse sum. One CTA per t; covers ALL 2048 u.
__global__ void __launch_bounds__(256) k_proj2(const float* __restrict__ x,
                                               const float* __restrict__ bias) {
    __shared__ float xs[Fv * Bv];   // [f][b]
    int t = blockIdx.x, tid = threadIdx.x;
    for (int i = tid; i < Fv * Bv; i += 256) {
        int b = i >> 7, f = i & 127;
        xs[f * Bv + b] = x[((size_t)b * Tv + t) * Fv + f];
    }
    __syncthreads();
    int bp = tid & 7;
    for (int uc = 0; uc < 64; uc++) {
        int u = uc * 32 + (tid >> 3);
        int n = g_cn[u];
        u64 acc = dup32(bias[u]);
        for (int j = 0; j < n; j++) {
            int f = g_ci[u * 16 + j];
            float v = g_cv[u * 16 + j];
            u64 xv = *(const u64*)&xs[f * Bv + 2 * bp];
            fma2(acc, dup32(v), xv);
        }
        *(u64*)(g_u + ((size_t)t * Uv + u) * Bv + 2 * bp) = acc;
    }
}

// persistent recurrence: cta owns cols [cta*16, cta*16+16)
__global__ void __launch_bounds__(256, 1) k_main(const float* __restrict__ W) {
    extern __shared__ float sm[];
    float* sW = sm;                    // [16 col][2052 k]
    float* hs = sm + CPC * WSTR;       // [2][256 k][16 b]
    unsigned hsb = sptr(hs);
    int tid = threadIdx.x, cta = blockIdx.x, cg0 = cta * CPC;
    for (int i = tid; i < Uv * CPC; i += 256) {
        int k = i >> 4, col = i & 15;
        sW[col * WSTR + k] = W[(size_t)k * Uv + cg0 + col];
    }
    __syncthreads();
    int par = tid >> 7, col = (tid >> 3) & 15, bp = tid & 7;
    const float* wrow = sW + col * WSTR + 4 * par;

    for (int t = 0; t < Tv; t++) {
        const float* hb = g_h[t & 1];
        u64 uval = 0;
        if (par == 0)
            uval = *(const u64*)(g_u + ((size_t)t * Uv + cg0 + col) * Bv + 2 * bp);
        // full 16 KB tile = 1024 x 16B = 4 cp.async per thread
        {
#pragma unroll
            for (int j = 0; j < 4; j++)
                cpa16(hsb + (unsigned)((tid + j * 256) * 16),
                      hb + (tid + j * 256) * 4);
            asm volatile("cp.async.commit_group;" ::: "memory");
        }
        u64 acc0 = 0, acc1 = 0;
        for (int tl = 0; tl < 8; tl++) {
            if (tl < 7) {
                unsigned base = hsb + (unsigned)(((tl + 1) & 1) * 16384);
                const float* src = hb + (tl + 1) * TK * Bv;
#pragma unroll
                for (int j = 0; j < 4; j++)
                    cpa16(base + (unsigned)((tid + j * 256) * 16),
                          src + (tid + j * 256) * 4);
            }
            asm volatile("cp.async.commit_group;" ::: "memory");
            asm volatile("cp.async.wait_group 1;" ::: "memory");
            __syncthreads();
            const float* hrow = hs + ((tl & 1) * 4096) + 2 * bp;
            const float* wr = wrow + tl * TK;
#pragma unroll 8
            for (int i = 0; i < 32; i++) {
                int k = 8 * i;
                float4 wv = *(const float4*)(wr + k);
                u64 h0 = *(const u64*)(hrow + (k + 4 * par + 0) * Bv);
                u64 h1 = *(const u64*)(hrow + (k + 4 * par + 1) * Bv);
                u64 h2 = *(const u64*)(hrow + (k + 4 * par + 2) * Bv);
                u64 h3 = *(const u64*)(hrow + (k + 4 * par + 3) * Bv);
                fma2(acc0, dup32(wv.x), h0);
                fma2(acc1, dup32(wv.y), h1);
                fma2(acc0, dup32(wv.z), h2);
                fma2(acc1, dup32(wv.w), h3);
            }
            __syncthreads();
        }
        add2(acc0, acc1);
        u64* red = (u64*)hs;
        if (par == 1) red[col * 8 + bp] = acc0;
        __syncthreads();
        if (par == 0) {
            add2(acc0, red[col * 8 + bp]);
            add2(acc0, uval);
            float lo = __uint_as_float((unsigned)(acc0 & 0xFFFFFFFFull));
            float hi = __uint_as_float((unsigned)(acc0 >> 32));
            float2 hn = make_float2(tanhf(lo), tanhf(hi));
            *(float2*)(g_h[(t + 1) & 1] + (cg0 + col) * Bv + 2 * bp) = hn;
        }
        __syncthreads();
        if (t < Tv - 1) {               // final barrier unnecessary (k_out is stream-ordered)
            if (tid == 0) {
                asm volatile("red.release.gpu.global.add.u32 [%0], %1;"
                             :: "l"(&g_bar), "r"(1u) : "memory");
                unsigned tgt = (unsigned)(NCTA * (t + 1));
                while (ldacq(&g_bar) < tgt) {}
            }
            __syncthreads();
        }
    }
}

__global__ void k_out(const float* __restrict__ w_out,
                      const float* __restrict__ b_out, float* __restrict__ out) {
    int b = threadIdx.x >> 5, lane = threadIdx.x & 31;
    float s = 0.0f;
    for (int u = lane; u < Uv; u += 32) s += g_h[0][u * Bv + b] * w_out[u];
#pragma unroll
    for (int o = 16; o; o >>= 1) s += __shfl_xor_sync(0xFFFFFFFFu, s, o);
    if (lane == 0) out[b] = s + b_out[0];
}

extern "C" void kernel_launch(void* const* d_in, const int* in_sizes, int n_in,
                              void* d_out, int out_size) {
    const float* x     = (const float*)d_in[0];
    const float* kern  = (const float*)d_in[1];
    const float* W     = (const float*)d_in[2];
    const float* bias  = (const float*)d_in[3];
    const float* w_out = (const float*)d_in[4];
    const float* b_out = (const float*)d_in[5];
    cudaFuncSetAttribute(k_main, cudaFuncAttributeMaxDynamicSharedMemorySize, SMEM_MAIN);
    k0<<<128, 256>>>();
    k_csc<<<8, 256>>>(kern);
    k_proj2<<<Tv, 256>>>(x, bias);
    k_main<<<NCTA, 256, SMEM_MAIN>>>(W);
    k_out<<<1, 512>>>(w_out, b_out, (float*)d_out);
}

// round 11
// speedup vs baseline: 1.9675x; 1.9675x over previous
#include <cuda_runtime.h>
#include <cstdint>

#define Uv 2048
#define Bv 16
#define Tv 2048
#define Fv 128
#define NCTA 128
#define CPC 16
#define TK 256
#define THR 512
#define SMEM_MAIN (Uv*CPC*4 + 2*TK*Bv*4)   // 128KB W + 32KB h tiles = 160KB

typedef unsigned long long u64;

__device__ __align__(16) float g_u[(size_t)Tv * Uv * Bv];   // [t][u][b]
__device__ __align__(16) float g_h[2][Uv * Bv];             // [buf][u][b]
__device__ unsigned g_bar;
__device__ int   g_ci[Uv * 16];
__device__ float g_cv[Uv * 16];
__device__ int   g_cn[Uv];

__device__ __forceinline__ void fma2(u64& d, u64 a, u64 b) {
    asm("fma.rn.f32x2 %0, %1, %2, %0;" : "+l"(d) : "l"(a), "l"(b));
}
__device__ __forceinline__ void add2(u64& d, u64 a) {
    asm("add.rn.f32x2 %0, %1, %0;" : "+l"(d) : "l"(a));
}
__device__ __forceinline__ u64 dup32(float x) {
    u64 d; unsigned xi = __float_as_uint(x);
    asm("mov.b64 %0, {%1, %1};" : "=l"(d) : "r"(xi)); return d;
}
__device__ __forceinline__ unsigned sptr(const void* p) {
    unsigned r;
    asm("{ .reg .u64 t; cvta.to.shared.u64 t, %1; cvt.u32.u64 %0, t; }" : "=r"(r) : "l"(p));
    return r;
}
__device__ __forceinline__ void cpa16(unsigned dst, const float* src) {
    asm volatile("cp.async.cg.shared.global [%0], [%1], 16;" :: "r"(dst), "l"(src));
}
__device__ __forceinline__ unsigned ldacq(unsigned* p) {
    unsigned v;
    asm volatile("ld.acquire.gpu.u32 %0, [%1];" : "=r"(v) : "l"(p) : "memory");
    return v;
}
__device__ __forceinline__ u64 shfl_xor64(u64 v, int d) {
    unsigned lo = (unsigned)v, hi = (unsigned)(v >> 32);
    lo = __shfl_xor_sync(0xFFFFFFFFu, lo, d);
    hi = __shfl_xor_sync(0xFFFFFFFFu, hi, d);
    return (u64)lo | ((u64)hi << 32);
}

__global__ void k0() {
    int i = blockIdx.x * blockDim.x + threadIdx.x;
    if (i == 0) g_bar = 0u;
    if (i < Uv * Bv) g_h[0][i] = 0.0f;
}

__global__ void k_csc(const float* __restrict__ kern) {
    int u = blockIdx.x * blockDim.x + threadIdx.x;
    if (u >= Uv) return;
    int c = 0;
    for (int f = 0; f < Fv; f++) {
        float v = kern[(size_t)f * Uv + u];
        if (v != 0.0f) { g_ci[u * 16 + c] = f; g_cv[u * 16 + c] = v; c++; }
    }
    g_cn[u] = c;
}

__global__ void __launch_bounds__(256) k_proj2(const float* __restrict__ x,
                                               const float* __restrict__ bias) {
    __shared__ float xs[Fv * Bv];
    int t = blockIdx.x, tid = threadIdx.x;
    for (int i = tid; i < Fv * Bv; i += 256) {
        int b = i >> 7, f = i & 127;
        xs[f * Bv + b] = x[((size_t)b * Tv + t) * Fv + f];
    }
    __syncthreads();
    int bp = tid & 7;
    for (int uc = 0; uc < 64; uc++) {
        int u = uc * 32 + (tid >> 3);
        int n = g_cn[u];
        u64 acc = dup32(bias[u]);
        for (int j = 0; j < n; j++) {
            int f = g_ci[u * 16 + j];
            float v = g_cv[u * 16 + j];
            u64 xv = *(const u64*)&xs[f * Bv + 2 * bp];
            fma2(acc, dup32(v), xv);
        }
        *(u64*)(g_u + ((size_t)t * Uv + u) * Bv + 2 * bp) = acc;
    }
}

// persistent recurrence: cta owns cols [cta*16, cta*16+16), 512 threads
__global__ void __launch_bounds__(THR, 1) k_main(const float* __restrict__ W) {
    extern __shared__ float sm[];
    float* sW = sm;                      // [2048 k][16 col]
    float* hs = sm + Uv * CPC;           // 2 x [256 k][16 b]
    unsigned hsb = sptr(hs);
    int tid = threadIdx.x, cta = blockIdx.x, cg0 = cta * CPC;
    int lane = tid & 31;
    int cg = lane & 3, ko = lane >> 2;   // cg:0..3 (col quad), ko:0..7 (k offset)
    int kp = tid >> 5;                   // warp id 0..15 (k-par)

    // prologue: sW[k][c] = W[k][cg0+c]
    for (int idx = tid; idx < Uv * CPC / 4; idx += THR) {
        int k = idx >> 2, c4 = idx & 3;
        float4 v = *(const float4*)(W + (size_t)k * Uv + cg0 + c4 * 4);
        *(float4*)(sW + k * CPC + c4 * 4) = v;
    }
    __syncthreads();

    for (int t = 0; t < Tv; t++) {
        const float* hb = g_h[t & 1];
        u64 uval = 0;
        if (tid < 128)
            uval = *(const u64*)(g_u + ((size_t)t * Uv + cg0 + (tid >> 3)) * Bv + 2 * (tid & 7));
        // prefetch tile 0 (16KB)
        cpa16(hsb + (unsigned)(tid * 16), hb + tid * 4);
        cpa16(hsb + (unsigned)((tid + 512) * 16), hb + (tid + 512) * 4);
        asm volatile("cp.async.commit_group;" ::: "memory");

        u64 acc[32];
#pragma unroll
        for (int i = 0; i < 32; i++) acc[i] = 0ull;

        for (int tl = 0; tl < 8; tl++) {
            if (tl < 7) {
                unsigned d = hsb + (unsigned)(((tl + 1) & 1) * 16384);
                const float* src = hb + (tl + 1) * TK * Bv;
                cpa16(d + (unsigned)(tid * 16), src + tid * 4);
                cpa16(d + (unsigned)((tid + 512) * 16), src + (tid + 512) * 4);
                asm volatile("cp.async.commit_group;" ::: "memory");
                asm volatile("cp.async.wait_group 1;" ::: "memory");
            } else {
                asm volatile("cp.async.wait_group 0;" ::: "memory");
            }
            __syncthreads();
            const float* hbuf = hs + (tl & 1) * 4096;   // floats
#pragma unroll
            for (int i = 0; i < 2; i++) {
                int kl = kp * 16 + i * 8 + ko;          // 0..255
                int gk = tl * TK + kl;
                // plain C++ derefs: compiler-ordered vs __syncthreads (LDS.128)
                float4 wv = *((const float4*)(sW + gk * CPC) + cg);
                u64 wd[4] = { dup32(wv.x), dup32(wv.y), dup32(wv.z), dup32(wv.w) };
                const ulonglong2* hp = (const ulonglong2*)(hbuf + kl * Bv);
                ulonglong2 p0 = hp[0], p1 = hp[1], p2 = hp[2], p3 = hp[3];
                u64 h[8] = { p0.x, p0.y, p1.x, p1.y, p2.x, p2.y, p3.x, p3.y };
#pragma unroll
                for (int c = 0; c < 4; c++)
#pragma unroll
                    for (int bp = 0; bp < 8; bp++)
                        fma2(acc[c * 8 + bp], wd[c], h[bp]);
            }
            __syncthreads();
        }

        // reduce-scatter over ko: lane ko ends owning acc[0..3] = flat idx [4ko..4ko+3]
#pragma unroll
        for (int m = 0; m < 16; m++) {
            u64 mine = (ko & 4) ? acc[16 + m] : acc[m];
            u64 send = (ko & 4) ? acc[m] : acc[16 + m];
            u64 r = shfl_xor64(send, 16);
            add2(mine, r); acc[m] = mine;
        }
#pragma unroll
        for (int m = 0; m < 8; m++) {
            u64 mine = (ko & 2) ? acc[8 + m] : acc[m];
            u64 send = (ko & 2) ? acc[m] : acc[8 + m];
            u64 r = shfl_xor64(send, 8);
            add2(mine, r); acc[m] = mine;
        }
#pragma unroll
        for (int m = 0; m < 4; m++) {
            u64 mine = (ko & 1) ? acc[4 + m] : acc[m];
            u64 send = (ko & 1) ? acc[m] : acc[4 + m];
            u64 r = shfl_xor64(send, 4);
            add2(mine, r); acc[m] = mine;
        }
        // stash partials: red[kp][o], o = col*8+bp, col = 4cg+(ko>>1), bp base = (ko&1)*4
        {
            u64* red = (u64*)hs;   // reuse buffer0: last read was tl=6, synced since
            int o0 = (4 * cg + (ko >> 1)) * 8 + (ko & 1) * 4;
            u64* dst = red + kp * 128 + o0;
            dst[0] = acc[0]; dst[1] = acc[1]; dst[2] = acc[2]; dst[3] = acc[3];
        }
        __syncthreads();
        if (tid < 128) {
            u64* red = (u64*)hs;
            u64 s = uval;
#pragma unroll
            for (int k2 = 0; k2 < 16; k2++) add2(s, red[k2 * 128 + tid]);
            float lo = __uint_as_float((unsigned)(s & 0xFFFFFFFFull));
            float hi = __uint_as_float((unsigned)(s >> 32));
            float2 hn = make_float2(tanhf(lo), tanhf(hi));
            *(float2*)(g_h[(t + 1) & 1] + (cg0 + (tid >> 3)) * Bv + 2 * (tid & 7)) = hn;
        }
        __syncthreads();
        if (t < Tv - 1) {
            if (tid == 0) {
                asm volatile("red.release.gpu.global.add.u32 [%0], %1;"
                             :: "l"(&g_bar), "r"(1u) : "memory");
                unsigned tgt = (unsigned)(NCTA * (t + 1));
                while (ldacq(&g_bar) < tgt) {}
            }
            __syncthreads();
        }
    }
}

__global__ void k_out(const float* __restrict__ w_out,
                      const float* __restrict__ b_out, float* __restrict__ out) {
    int b = threadIdx.x >> 5, lane = threadIdx.x & 31;
    float s = 0.0f;
    for (int u = lane; u < Uv; u += 32) s += g_h[0][u * Bv + b] * w_out[u];
#pragma unroll
    for (int o = 16; o; o >>= 1) s += __shfl_xor_sync(0xFFFFFFFFu, s, o);
    if (lane == 0) out[b] = s + b_out[0];
}

extern "C" void kernel_launch(void* const* d_in, const int* in_sizes, int n_in,
                              void* d_out, int out_size) {
    const float* x     = (const float*)d_in[0];
    const float* kern  = (const float*)d_in[1];
    const float* W     = (const float*)d_in[2];
    const float* bias  = (const float*)d_in[3];
    const float* w_out = (const float*)d_in[4];
    const float* b_out = (const float*)d_in[5];
    cudaFuncSetAttribute(k_main, cudaFuncAttributeMaxDynamicSharedMemorySize, SMEM_MAIN);
    k0<<<128, 256>>>();
    k_csc<<<8, 256>>>(kern);
    k_proj2<<<Tv, 256>>>(x, bias);
    k_main<<<NCTA, THR, SMEM_MAIN>>>(W);
    k_out<<<1, 512>>>(w_out, b_out, (float*)d_out);
}

// round 12
// speedup vs baseline: 2.0840x; 1.0592x over previous
#include <cuda_runtime.h>
#include <cstdint>

#define Uv 2048
#define Bv 16
#define Tv 2048
#define Fv 128
#define NCTA 128
#define CPC 16
#define TK 512
#define THR 512
#define SMEM_MAIN (Uv*CPC*4 + 3*TK*Bv*4)   // 128KB W + 96KB h ring = 224KB

typedef unsigned long long u64;

__device__ __align__(16) float g_u[(size_t)Tv * Uv * Bv];   // [t][u][b]
__device__ __align__(16) float g_h[2][Uv * Bv];             // [buf][u][b]
__device__ unsigned g_bar;
__device__ int   g_ci[Uv * 16];
__device__ float g_cv[Uv * 16];
__device__ int   g_cn[Uv];

__device__ __forceinline__ void fma2(u64& d, u64 a, u64 b) {
    asm("fma.rn.f32x2 %0, %1, %2, %0;" : "+l"(d) : "l"(a), "l"(b));
}
__device__ __forceinline__ void add2(u64& d, u64 a) {
    asm("add.rn.f32x2 %0, %1, %0;" : "+l"(d) : "l"(a));
}
__device__ __forceinline__ u64 dup32(float x) {
    u64 d; unsigned xi = __float_as_uint(x);
    asm("mov.b64 %0, {%1, %1};" : "=l"(d) : "r"(xi)); return d;
}
__device__ __forceinline__ unsigned sptr(const void* p) {
    unsigned r;
    asm("{ .reg .u64 t; cvta.to.shared.u64 t, %1; cvt.u32.u64 %0, t; }" : "=r"(r) : "l"(p));
    return r;
}
__device__ __forceinline__ void cpa16(unsigned dst, const float* src) {
    asm volatile("cp.async.cg.shared.global [%0], [%1], 16;" :: "r"(dst), "l"(src));
}
__device__ __forceinline__ unsigned ldacq(unsigned* p) {
    unsigned v;
    asm volatile("ld.acquire.gpu.u32 %0, [%1];" : "=r"(v) : "l"(p) : "memory");
    return v;
}
__device__ __forceinline__ u64 shfl_xor64(u64 v, int d) {
    unsigned lo = (unsigned)v, hi = (unsigned)(v >> 32);
    lo = __shfl_xor_sync(0xFFFFFFFFu, lo, d);
    hi = __shfl_xor_sync(0xFFFFFFFFu, hi, d);
    return (u64)lo | ((u64)hi << 32);
}

__global__ void k0() {
    int i = blockIdx.x * blockDim.x + threadIdx.x;
    if (i == 0) g_bar = 0u;
    if (i < Uv * Bv) g_h[0][i] = 0.0f;
}

__global__ void k_csc(const float* __restrict__ kern) {
    int u = blockIdx.x * blockDim.x + threadIdx.x;
    if (u >= Uv) return;
    int c = 0;
    for (int f = 0; f < Fv; f++) {
        float v = kern[(size_t)f * Uv + u];
        if (v != 0.0f) { g_ci[u * 16 + c] = f; g_cv[u * 16 + c] = v; c++; }
    }
    g_cn[u] = c;
}

__global__ void __launch_bounds__(256) k_proj2(const float* __restrict__ x,
                                               const float* __restrict__ bias) {
    __shared__ float xs[Fv * Bv];
    int t = blockIdx.x, tid = threadIdx.x;
    for (int i = tid; i < Fv * Bv; i += 256) {
        int b = i >> 7, f = i & 127;
        xs[f * Bv + b] = x[((size_t)b * Tv + t) * Fv + f];
    }
    __syncthreads();
    int bp = tid & 7;
    for (int uc = 0; uc < 64; uc++) {
        int u = uc * 32 + (tid >> 3);
        int n = g_cn[u];
        u64 acc = dup32(bias[u]);
        for (int j = 0; j < n; j++) {
            int f = g_ci[u * 16 + j];
            float v = g_cv[u * 16 + j];
            u64 xv = *(const u64*)&xs[f * Bv + 2 * bp];
            fma2(acc, dup32(v), xv);
        }
        *(u64*)(g_u + ((size_t)t * Uv + u) * Bv + 2 * bp) = acc;
    }
}

// persistent recurrence: cta owns cols [cta*16, cta*16+16), 512 threads
// 4 k-tiles of 512, 3-deep smem ring, ONE syncthreads per tile.
__global__ void __launch_bounds__(THR, 1) k_main(const float* __restrict__ W) {
    extern __shared__ float sm[];
    float* sW = sm;                      // [2048 k][16 col]
    float* hs = sm + Uv * CPC;           // 3 x [512 k][16 b] (32KB each)
    unsigned hsb = sptr(hs);
    int tid = threadIdx.x, cta = blockIdx.x, cg0 = cta * CPC;
    int lane = tid & 31;
    int cg = lane & 3, ko = lane >> 2;   // cg:0..3 (col quad), ko:0..7 (k offset)
    int kp = tid >> 5;                   // warp id 0..15

    for (int idx = tid; idx < Uv * CPC / 4; idx += THR) {
        int k = idx >> 2, c4 = idx & 3;
        float4 v = *(const float4*)(W + (size_t)k * Uv + cg0 + c4 * 4);
        *(float4*)(sW + k * CPC + c4 * 4) = v;
    }
    __syncthreads();

    for (int t = 0; t < Tv; t++) {
        const float* hb = g_h[t & 1];
        u64 uval = 0;
        if (tid < 128)
            uval = *(const u64*)(g_u + ((size_t)t * Uv + cg0 + (tid >> 3)) * Bv + 2 * (tid & 7));
        // prefetch tile 0 into ring slot 0 (32KB = 4 cp.async per thread)
#pragma unroll
        for (int j = 0; j < 4; j++)
            cpa16(hsb + (unsigned)((tid + j * THR) * 16), hb + (tid + j * THR) * 4);
        asm volatile("cp.async.commit_group;" ::: "memory");

        u64 acc[32];
#pragma unroll
        for (int i = 0; i < 32; i++) acc[i] = 0ull;

        for (int tl = 0; tl < 4; tl++) {
            if (tl < 3) {
                int slot = (tl + 1) % 3;
                unsigned d = hsb + (unsigned)(slot * TK * Bv * 4);
                const float* src = hb + (tl + 1) * TK * Bv;
#pragma unroll
                for (int j = 0; j < 4; j++)
                    cpa16(d + (unsigned)((tid + j * THR) * 16), src + (tid + j * THR) * 4);
                asm volatile("cp.async.commit_group;" ::: "memory");
                asm volatile("cp.async.wait_group 1;" ::: "memory");
            } else {
                asm volatile("cp.async.wait_group 0;" ::: "memory");
            }
            __syncthreads();
            const float* hbuf = hs + (tl % 3) * (TK * Bv);
#pragma unroll
            for (int i = 0; i < 4; i++) {
                int kl = kp * 32 + i * 8 + ko;          // 0..511
                int gk = tl * TK + kl;
                float4 wv = *((const float4*)(sW + gk * CPC) + cg);
                u64 wd[4] = { dup32(wv.x), dup32(wv.y), dup32(wv.z), dup32(wv.w) };
                const ulonglong2* hp = (const ulonglong2*)(hbuf + kl * Bv);
                ulonglong2 p0 = hp[0], p1 = hp[1], p2 = hp[2], p3 = hp[3];
                u64 h[8] = { p0.x, p0.y, p1.x, p1.y, p2.x, p2.y, p3.x, p3.y };
#pragma unroll
                for (int c = 0; c < 4; c++)
#pragma unroll
                    for (int bp = 0; bp < 8; bp++)
                        fma2(acc[c * 8 + bp], wd[c], h[bp]);
            }
        }

        // reduce-scatter over ko: lane ko ends owning acc[0..3] = flat idx [4ko..4ko+3]
#pragma unroll
        for (int m = 0; m < 16; m++) {
            u64 mine = (ko & 4) ? acc[16 + m] : acc[m];
            u64 send = (ko & 4) ? acc[m] : acc[16 + m];
            u64 r = shfl_xor64(send, 16);
            add2(mine, r); acc[m] = mine;
        }
#pragma unroll
        for (int m = 0; m < 8; m++) {
            u64 mine = (ko & 2) ? acc[8 + m] : acc[m];
            u64 send = (ko & 2) ? acc[m] : acc[8 + m];
            u64 r = shfl_xor64(send, 8);
            add2(mine, r); acc[m] = mine;
        }
#pragma unroll
        for (int m = 0; m < 4; m++) {
            u64 mine = (ko & 1) ? acc[4 + m] : acc[m];
            u64 send = (ko & 1) ? acc[m] : acc[4 + m];
            u64 r = shfl_xor64(send, 4);
            add2(mine, r); acc[m] = mine;
        }
        __syncthreads();   // guard: ring slot 0 (stash target) holds tile-3 data being read
        // stash partials: red[kp][o], o = col*8+bp, col = 4cg+(ko>>1), bp base = (ko&1)*4
        {
            u64* red = (u64*)hs;
            int o0 = (4 * cg + (ko >> 1)) * 8 + (ko & 1) * 4;
            u64* dst = red + kp * 128 + o0;
            dst[0] = acc[0]; dst[1] = acc[1]; dst[2] = acc[2]; dst[3] = acc[3];
        }
        __syncthreads();
        if (tid < 128) {
            u64* red = (u64*)hs;
            u64 s = uval;
#pragma unroll
            for (int k2 = 0; k2 < 16; k2++) add2(s, red[k2 * 128 + tid]);
            float lo = __uint_as_float((unsigned)(s & 0xFFFFFFFFull));
            float hi = __uint_as_float((unsigned)(s >> 32));
            float2 hn = make_float2(tanhf(lo), tanhf(hi));
            *(float2*)(g_h[(t + 1) & 1] + (cg0 + (tid >> 3)) * Bv + 2 * (tid & 7)) = hn;
        }
        __syncthreads();
        if (t < Tv - 1) {
            if (tid == 0) {
                asm volatile("red.release.gpu.global.add.u32 [%0], %1;"
                             :: "l"(&g_bar), "r"(1u) : "memory");
                unsigned tgt = (unsigned)(NCTA * (t + 1));
                while (ldacq(&g_bar) < tgt) {}
            }
            __syncthreads();
        }
    }
}

__global__ void k_out(const float* __restrict__ w_out,
                      const float* __restrict__ b_out, float* __restrict__ out) {
    int b = threadIdx.x >> 5, lane = threadIdx.x & 31;
    float s = 0.0f;
    for (int u = lane; u < Uv; u += 32) s += g_h[0][u * Bv + b] * w_out[u];
#pragma unroll
    for (int o = 16; o; o >>= 1) s += __shfl_xor_sync(0xFFFFFFFFu, s, o);
    if (lane == 0) out[b] = s + b_out[0];
}

extern "C" void kernel_launch(void* const* d_in, const int* in_sizes, int n_in,
                              void* d_out, int out_size) {
    const float* x     = (const float*)d_in[0];
    const float* kern  = (const float*)d_in[1];
    const float* W     = (const float*)d_in[2];
    const float* bias  = (const float*)d_in[3];
    const float* w_out = (const float*)d_in[4];
    const float* b_out = (const float*)d_in[5];
    cudaFuncSetAttribute(k_main, cudaFuncAttributeMaxDynamicSharedMemorySize, SMEM_MAIN);
    k0<<<128, 256>>>();
    k_csc<<<8, 256>>>(kern);
    k_proj2<<<Tv, 256>>>(x, bias);
    k_main<<<NCTA, THR, SMEM_MAIN>>>(W);
    k_out<<<1, 512>>>(w_out, b_out, (float*)d_out);
}